// round 2
// baseline (speedup 1.0000x reference)
#include <cuda_runtime.h>
#include <cuda_bf16.h>

// Scratch accumulators (device globals; no allocation allowed)
__device__ float g_sV[8192];     // sV = W_next @ V_next    [N]
__device__ float g_pP[8192];     // pi @ P_i                [K]
__device__ float g_pPh[8192];    // pi @ P_hat_i            [K]

__global__ void zero_kernel(int k) {
    int i = blockIdx.x * blockDim.x + threadIdx.x;
    if (i < k) { g_pP[i] = 0.0f; g_pPh[i] = 0.0f; }
}

// Fused matvec kernel.
// Job layout in blockIdx.x: [nWBlocks: W rows][nPBlocks: P cols][nPBlocks: Ph cols]
//
// W job   : sV[i] = dot(W[i, :], V)   — one warp per row, row-contiguous float4
//           loads, warp shuffle reduction, direct store (no atomics).
// P jobs  : out[k] += sum_{r in chunk} pi[r] * M[r, k] — split-K column
//           reduction, 256 threads x float4 = 1024 cols per block, atomicAdd.
__global__ __launch_bounds__(256, 8)
void matvec_kernel(const float* __restrict__ W,  const float* __restrict__ Vn,
                   const float* __restrict__ P,  const float* __restrict__ Ph,
                   const float* __restrict__ pi,
                   int N, int Nnext, int K, int Prows,
                   int nWBlocks, int pColTiles, int pRowChunks) {
    int b = blockIdx.x;
    const int nPBlocks = pColTiles * pRowChunks;

    if (b < nWBlocks) {
        // ---- W row-reduction: 8 warps per block, 1 row per warp ----
        const int warp = threadIdx.x >> 5;
        const int lane = threadIdx.x & 31;
        const int row  = b * 8 + warp;
        if (row >= N) return;

        const float4* wr = reinterpret_cast<const float4*>(W + (size_t)row * Nnext);
        const float4* vv = reinterpret_cast<const float4*>(Vn);
        const int iters = Nnext / (32 * 4);      // 4096 / 128 = 32

        float acc = 0.0f;
        #pragma unroll 4
        for (int it = 0; it < iters; ++it) {
            int idx = it * 32 + lane;
            float4 w = __ldg(wr + idx);
            float4 v = __ldg(vv + idx);
            acc = fmaf(w.x, v.x, acc);
            acc = fmaf(w.y, v.y, acc);
            acc = fmaf(w.z, v.z, acc);
            acc = fmaf(w.w, v.w, acc);
        }
        #pragma unroll
        for (int o = 16; o > 0; o >>= 1)
            acc += __shfl_down_sync(0xFFFFFFFFu, acc, o);
        if (lane == 0) g_sV[row] = acc;
        return;
    }

    // ---- P / P_hat column reductions ----
    b -= nWBlocks;
    const float* mat; float* out;
    if (b < nPBlocks) { mat = P;  out = g_pP;  }
    else              { mat = Ph; out = g_pPh; b -= nPBlocks; }

    const int ROWS_PER_CHUNK = 128;
    const int colTile  = b % pColTiles;
    const int rowChunk = b / pColTiles;
    const int col = colTile * 1024 + threadIdx.x * 4;
    const int r0  = rowChunk * ROWS_PER_CHUNK;

    const float4* m = reinterpret_cast<const float4*>(mat + (size_t)r0 * K + col);
    const size_t stride4 = (size_t)K / 4;

    float4 acc = make_float4(0.f, 0.f, 0.f, 0.f);
    #pragma unroll 8
    for (int r = 0; r < ROWS_PER_CHUNK; ++r) {
        float  v = __ldg(pi + r0 + r);
        float4 w = __ldg(m);
        acc.x = fmaf(v, w.x, acc.x);
        acc.y = fmaf(v, w.y, acc.y);
        acc.z = fmaf(v, w.z, acc.z);
        acc.w = fmaf(v, w.w, acc.w);
        m += stride4;
    }
    atomicAdd(&out[col + 0], acc.x);
    atomicAdd(&out[col + 1], acc.y);
    atomicAdd(&out[col + 2], acc.z);
    atomicAdd(&out[col + 3], acc.w);
}

// Single-block epilogue: block-wide exclusive scan of the unstable mask gives
// each unstable neuron its rank k into pP/pPh/alpha, then fused output write.
__global__ __launch_bounds__(1024, 1)
void epilogue_kernel(const float* __restrict__ C, const float* __restrict__ L,
                     const float* __restrict__ U, const float* __restrict__ alpha,
                     float* __restrict__ out, int N, int K) {
    const int tid  = threadIdx.x;
    const int base = tid * 4;                    // N <= 4096, 1024 threads
    const int lane = tid & 31, warp = tid >> 5;

    float l[4], u[4];
    int un[4];
    int cnt = 0;
    #pragma unroll
    for (int i = 0; i < 4; ++i) {
        int n = base + i;
        if (n < N) {
            l[i] = L[n]; u[i] = U[n];
            un[i] = (l[i] < 0.0f) && (u[i] > 0.0f);
        } else { l[i] = 0.f; u[i] = 0.f; un[i] = 0; }
        cnt += un[i];
    }

    // inclusive warp scan of per-thread counts
    int inc = cnt;
    #pragma unroll
    for (int o = 1; o < 32; o <<= 1) {
        int t = __shfl_up_sync(0xFFFFFFFFu, inc, o);
        if (lane >= o) inc += t;
    }
    __shared__ int warpBase[32];
    if (lane == 31) warpBase[warp] = inc;
    __syncthreads();
    if (warp == 0) {
        int s = warpBase[lane];
        int is = s;
        #pragma unroll
        for (int o = 1; o < 32; o <<= 1) {
            int t = __shfl_up_sync(0xFFFFFFFFu, is, o);
            if (lane >= o) is += t;
        }
        warpBase[lane] = is - s;   // exclusive across warps
    }
    __syncthreads();

    int k = (inc - cnt) + warpBase[warp];        // exclusive prefix for this thread

    #pragma unroll
    for (int i = 0; i < 4; ++i) {
        int n = base + i;
        if (n >= N) break;
        float c = C[n];
        float val;
        if (un[i]) {
            if (k < K) {
                float vhat = g_sV[n] - g_pPh[k];
                float rp   = fmaxf(vhat, 0.0f);
                float rn   = fmaxf(-vhat, 0.0f);
                val = rp * u[i] / (u[i] - l[i]) - c - alpha[k] * rn - g_pP[k];
            } else {
                val = 0.0f;  // reference's nonzero() would truncate these
            }
            ++k;
        } else if (u[i] <= 0.0f) {
            val = -c;                            // stably deactivated (wins over act)
        } else if (l[i] >= 0.0f) {
            val = g_sV[n] - c;                   // stably activated
        } else {
            val = 0.0f;
        }
        out[n] = val;
    }
}

extern "C" void kernel_launch(void* const* d_in, const int* in_sizes, int n_in,
                              void* d_out, int out_size) {
    const float* Vn    = (const float*)d_in[0];   // [N_NEXT]
    const float* W     = (const float*)d_in[1];   // [N_NEXT, N]
    const float* C     = (const float*)d_in[2];   // [N]
    const float* L     = (const float*)d_in[3];   // [N]
    const float* U     = (const float*)d_in[4];   // [N]
    const float* P     = (const float*)d_in[5];   // [P_ROWS, K]
    const float* Ph    = (const float*)d_in[6];   // [P_ROWS, K]
    const float* pi    = (const float*)d_in[7];   // [P_ROWS]
    const float* alpha = (const float*)d_in[8];   // [K]
    float* out = (float*)d_out;

    const int Nnext = in_sizes[0];
    const int N     = in_sizes[2];
    const int Prows = in_sizes[7];
    const int K     = in_sizes[8];

    const int ROWS_PER_CHUNK = 128;
    const int COLS_PER_BLOCK = 1024;
    int nWBlocks   = (N + 7) / 8;                 // 512 (warp per row, 8 warps/block)
    int pColTiles  = K / COLS_PER_BLOCK;          // 2
    int pRowChunks = Prows / ROWS_PER_CHUNK;      // 64

    zero_kernel<<<(K + 255) / 256, 256>>>(K);

    int nBlocks = nWBlocks + 2 * pColTiles * pRowChunks;  // 512 + 256 = 768
    matvec_kernel<<<nBlocks, 256>>>(W, Vn, P, Ph, pi, N, Nnext, K, Prows,
                                    nWBlocks, pColTiles, pRowChunks);

    epilogue_kernel<<<1, 1024>>>(C, L, U, alpha, out, N, K);
}

// round 3
// speedup vs baseline: 1.3741x; 1.3741x over previous
#include <cuda_runtime.h>
#include <cuda_bf16.h>

// Scratch accumulators (device globals; zero-initialized at module load,
// re-zeroed by the epilogue at the end of every kernel_launch sequence).
__device__ float g_sV[8192];     // sV = W_next @ V_next    [N]
__device__ float g_pP[8192];     // pi @ P_i                [K]
__device__ float g_pPh[8192];    // pi @ P_hat_i            [K]

// Fused matvec kernel.
// Job layout in blockIdx.x: [nWBlocks: W rows][nPBlocks: P cols][nPBlocks: Ph cols]
//
// W job : sV[i] = dot(W[i, :], V) — one warp per row; batches of 4 float4 W
//         loads + 4 float4 V loads issued back-to-back (MLP ~8), shuffle reduce.
// P job : out[k] += sum_{r in chunk} pi[r] * M[r, k] — split-K column
//         reduction; per batch 8 independent float4 matrix loads (MLP ~8).
__global__ __launch_bounds__(256)
void matvec_kernel(const float* __restrict__ W,  const float* __restrict__ Vn,
                   const float* __restrict__ P,  const float* __restrict__ Ph,
                   const float* __restrict__ pi,
                   int N, int Nnext, int K, int Prows,
                   int nWBlocks, int pColTiles, int pRowChunks) {
    int b = blockIdx.x;
    const int nPBlocks = pColTiles * pRowChunks;

    if (b < nWBlocks) {
        // ---- W row-reduction: 8 warps per block, 1 row per warp ----
        const int warp = threadIdx.x >> 5;
        const int lane = threadIdx.x & 31;
        const int row  = b * 8 + warp;
        if (row >= N) return;

        const float4* wr = reinterpret_cast<const float4*>(W + (size_t)row * Nnext) + lane;
        const float4* vv = reinterpret_cast<const float4*>(Vn) + lane;
        const int nBatch = Nnext / (32 * 4 * 4);      // 4096/512 = 8

        float acc = 0.0f;
        for (int it = 0; it < nBatch; ++it) {
            float4 w0 = __ldg(wr + 0 * 32);
            float4 w1 = __ldg(wr + 1 * 32);
            float4 w2 = __ldg(wr + 2 * 32);
            float4 w3 = __ldg(wr + 3 * 32);
            float4 v0 = __ldg(vv + 0 * 32);
            float4 v1 = __ldg(vv + 1 * 32);
            float4 v2 = __ldg(vv + 2 * 32);
            float4 v3 = __ldg(vv + 3 * 32);
            acc = fmaf(w0.x, v0.x, acc); acc = fmaf(w0.y, v0.y, acc);
            acc = fmaf(w0.z, v0.z, acc); acc = fmaf(w0.w, v0.w, acc);
            acc = fmaf(w1.x, v1.x, acc); acc = fmaf(w1.y, v1.y, acc);
            acc = fmaf(w1.z, v1.z, acc); acc = fmaf(w1.w, v1.w, acc);
            acc = fmaf(w2.x, v2.x, acc); acc = fmaf(w2.y, v2.y, acc);
            acc = fmaf(w2.z, v2.z, acc); acc = fmaf(w2.w, v2.w, acc);
            acc = fmaf(w3.x, v3.x, acc); acc = fmaf(w3.y, v3.y, acc);
            acc = fmaf(w3.z, v3.z, acc); acc = fmaf(w3.w, v3.w, acc);
            wr += 4 * 32;
            vv += 4 * 32;
        }
        #pragma unroll
        for (int o = 16; o > 0; o >>= 1)
            acc += __shfl_down_sync(0xFFFFFFFFu, acc, o);
        if (lane == 0) g_sV[row] = acc;
        return;
    }

    // ---- P / P_hat column reductions ----
    b -= nWBlocks;
    const float* mat; float* out;
    if (b < nPBlocks) { mat = P;  out = g_pP;  }
    else              { mat = Ph; out = g_pPh; b -= nPBlocks; }

    const int ROWS_PER_CHUNK = 128;
    const int colTile  = b % pColTiles;
    const int rowChunk = b / pColTiles;
    const int col = colTile * 1024 + threadIdx.x * 4;
    const int r0  = rowChunk * ROWS_PER_CHUNK;

    const float4* m = reinterpret_cast<const float4*>(mat + (size_t)r0 * K + col);
    const float4* p4 = reinterpret_cast<const float4*>(pi + r0);
    const size_t s4 = (size_t)K / 4;

    float4 acc = make_float4(0.f, 0.f, 0.f, 0.f);
    for (int rr = 0; rr < ROWS_PER_CHUNK; rr += 8) {
        // front-batch: 8 matrix float4 loads + 2 pi float4 loads (all independent)
        float4 w0 = __ldg(m + 0 * s4);
        float4 w1 = __ldg(m + 1 * s4);
        float4 w2 = __ldg(m + 2 * s4);
        float4 w3 = __ldg(m + 3 * s4);
        float4 w4 = __ldg(m + 4 * s4);
        float4 w5 = __ldg(m + 5 * s4);
        float4 w6 = __ldg(m + 6 * s4);
        float4 w7 = __ldg(m + 7 * s4);
        float4 pa = __ldg(p4 + 0);
        float4 pb = __ldg(p4 + 1);

        acc.x = fmaf(pa.x, w0.x, acc.x); acc.y = fmaf(pa.x, w0.y, acc.y);
        acc.z = fmaf(pa.x, w0.z, acc.z); acc.w = fmaf(pa.x, w0.w, acc.w);
        acc.x = fmaf(pa.y, w1.x, acc.x); acc.y = fmaf(pa.y, w1.y, acc.y);
        acc.z = fmaf(pa.y, w1.z, acc.z); acc.w = fmaf(pa.y, w1.w, acc.w);
        acc.x = fmaf(pa.z, w2.x, acc.x); acc.y = fmaf(pa.z, w2.y, acc.y);
        acc.z = fmaf(pa.z, w2.z, acc.z); acc.w = fmaf(pa.z, w2.w, acc.w);
        acc.x = fmaf(pa.w, w3.x, acc.x); acc.y = fmaf(pa.w, w3.y, acc.y);
        acc.z = fmaf(pa.w, w3.z, acc.z); acc.w = fmaf(pa.w, w3.w, acc.w);
        acc.x = fmaf(pb.x, w4.x, acc.x); acc.y = fmaf(pb.x, w4.y, acc.y);
        acc.z = fmaf(pb.x, w4.z, acc.z); acc.w = fmaf(pb.x, w4.w, acc.w);
        acc.x = fmaf(pb.y, w5.x, acc.x); acc.y = fmaf(pb.y, w5.y, acc.y);
        acc.z = fmaf(pb.y, w5.z, acc.z); acc.w = fmaf(pb.y, w5.w, acc.w);
        acc.x = fmaf(pb.z, w6.x, acc.x); acc.y = fmaf(pb.z, w6.y, acc.y);
        acc.z = fmaf(pb.z, w6.z, acc.z); acc.w = fmaf(pb.z, w6.w, acc.w);
        acc.x = fmaf(pb.w, w7.x, acc.x); acc.y = fmaf(pb.w, w7.y, acc.y);
        acc.z = fmaf(pb.w, w7.z, acc.z); acc.w = fmaf(pb.w, w7.w, acc.w);

        m  += 8 * s4;
        p4 += 2;
    }
    atomicAdd(&out[col + 0], acc.x);
    atomicAdd(&out[col + 1], acc.y);
    atomicAdd(&out[col + 2], acc.z);
    atomicAdd(&out[col + 3], acc.w);
}

// Single-block epilogue: block-wide exclusive scan of the unstable mask gives
// each unstable neuron its rank k into pP/pPh/alpha, then fused output write.
// At the end, re-zeros g_pP/g_pPh so the next graph replay starts clean.
__global__ __launch_bounds__(1024, 1)
void epilogue_kernel(const float* __restrict__ C, const float* __restrict__ L,
                     const float* __restrict__ U, const float* __restrict__ alpha,
                     float* __restrict__ out, int N, int K) {
    const int tid  = threadIdx.x;
    const int base = tid * 4;                    // N <= 4096, 1024 threads
    const int lane = tid & 31, warp = tid >> 5;

    float l[4], u[4];
    int un[4];
    int cnt = 0;
    #pragma unroll
    for (int i = 0; i < 4; ++i) {
        int n = base + i;
        if (n < N) {
            l[i] = L[n]; u[i] = U[n];
            un[i] = (l[i] < 0.0f) && (u[i] > 0.0f);
        } else { l[i] = 0.f; u[i] = 0.f; un[i] = 0; }
        cnt += un[i];
    }

    // inclusive warp scan of per-thread counts
    int inc = cnt;
    #pragma unroll
    for (int o = 1; o < 32; o <<= 1) {
        int t = __shfl_up_sync(0xFFFFFFFFu, inc, o);
        if (lane >= o) inc += t;
    }
    __shared__ int warpBase[32];
    if (lane == 31) warpBase[warp] = inc;
    __syncthreads();
    if (warp == 0) {
        int s = warpBase[lane];
        int is = s;
        #pragma unroll
        for (int o = 1; o < 32; o <<= 1) {
            int t = __shfl_up_sync(0xFFFFFFFFu, is, o);
            if (lane >= o) is += t;
        }
        warpBase[lane] = is - s;   // exclusive across warps
    }
    __syncthreads();

    int k = (inc - cnt) + warpBase[warp];        // exclusive prefix for this thread

    #pragma unroll
    for (int i = 0; i < 4; ++i) {
        int n = base + i;
        if (n >= N) break;
        float c = C[n];
        float val;
        if (un[i]) {
            if (k < K) {
                float vhat = g_sV[n] - g_pPh[k];
                float rp   = fmaxf(vhat, 0.0f);
                float rn   = fmaxf(-vhat, 0.0f);
                val = rp * u[i] / (u[i] - l[i]) - c - alpha[k] * rn - g_pP[k];
            } else {
                val = 0.0f;  // reference's nonzero() would truncate these
            }
            ++k;
        } else if (u[i] <= 0.0f) {
            val = -c;                            // stably deactivated (wins over act)
        } else if (l[i] >= 0.0f) {
            val = g_sV[n] - c;                   // stably activated
        } else {
            val = 0.0f;
        }
        out[n] = val;
    }

    // All reads of g_pP/g_pPh done -> re-zero for the next invocation.
    __syncthreads();
    for (int i = tid; i < K; i += 1024) {
        g_pP[i]  = 0.0f;
        g_pPh[i] = 0.0f;
    }
}

extern "C" void kernel_launch(void* const* d_in, const int* in_sizes, int n_in,
                              void* d_out, int out_size) {
    const float* Vn    = (const float*)d_in[0];   // [N_NEXT]
    const float* W     = (const float*)d_in[1];   // [N_NEXT, N]
    const float* C     = (const float*)d_in[2];   // [N]
    const float* L     = (const float*)d_in[3];   // [N]
    const float* U     = (const float*)d_in[4];   // [N]
    const float* P     = (const float*)d_in[5];   // [P_ROWS, K]
    const float* Ph    = (const float*)d_in[6];   // [P_ROWS, K]
    const float* pi    = (const float*)d_in[7];   // [P_ROWS]
    const float* alpha = (const float*)d_in[8];   // [K]
    float* out = (float*)d_out;

    const int Nnext = in_sizes[0];
    const int N     = in_sizes[2];
    const int Prows = in_sizes[7];
    const int K     = in_sizes[8];

    const int ROWS_PER_CHUNK = 128;
    const int COLS_PER_BLOCK = 1024;
    int nWBlocks   = (N + 7) / 8;                 // 512 (warp per row, 8 warps/block)
    int pColTiles  = K / COLS_PER_BLOCK;          // 2
    int pRowChunks = Prows / ROWS_PER_CHUNK;      // 64

    int nBlocks = nWBlocks + 2 * pColTiles * pRowChunks;  // 512 + 256 = 768
    matvec_kernel<<<nBlocks, 256>>>(W, Vn, P, Ph, pi, N, Nnext, K, Prows,
                                    nWBlocks, pColTiles, pRowChunks);

    epilogue_kernel<<<1, 1024>>>(C, L, U, alpha, out, N, K);
}

// round 4
// speedup vs baseline: 1.5482x; 1.1267x over previous
#include <cuda_runtime.h>
#include <cuda_bf16.h>

// Scratch accumulators (device globals; zero-initialized at module load).
// g_sV: plain stores, fully overwritten each replay.
// g_pP/g_pPh: atomically accumulated; consumed rank-ranges re-zeroed by the
// epilogue blocks that read them (block-exclusive, race-free).
__device__ float g_sV[8192];     // sV = W_next @ V_next    [N]
__device__ float g_pP[8192];     // pi @ P_i                [K]
__device__ float g_pPh[8192];    // pi @ P_hat_i            [K]

// Balanced fused matvec. Grid = 512 blocks x 256 threads.
// 1536 tiles of ~128KB: tile t -> type = t % 3 (0:W, 1:P, 2:Ph), idx = t / 3.
// Block b processes tiles {b, b+512, b+1024}: since 512 % 3 == 2, each block
// gets exactly one tile of each type -> identical 384KB of traffic per block.
//
// W tile (idx in [0,512)) : rows [idx*8, idx*8+8), one warp per row,
//                           batches of 4 float4 W + 4 float4 V (MLP ~8).
// P tile (idx in [0,512)) : colTile = idx&1 (1024 cols), rowChunk = idx>>1
//                           (32 rows), batches of 8 float4 rows (MLP ~8),
//                           atomicAdd partials.
__global__ __launch_bounds__(256, 4)
void matvec_kernel(const float* __restrict__ W,  const float* __restrict__ Vn,
                   const float* __restrict__ P,  const float* __restrict__ Ph,
                   const float* __restrict__ pi,
                   int N, int Nnext, int K, int Prows, int G) {
    #pragma unroll 1
    for (int i = 0; i < 3; ++i) {
        const int t    = blockIdx.x + G * i;
        const int type = t % 3;
        const int idx  = t / 3;

        if (type == 0) {
            // ---- W tile: 8 rows, warp per row ----
            const int warp = threadIdx.x >> 5;
            const int lane = threadIdx.x & 31;
            const int row  = idx * 8 + warp;

            const float4* wr = reinterpret_cast<const float4*>(W + (size_t)row * Nnext) + lane;
            const float4* vv = reinterpret_cast<const float4*>(Vn) + lane;
            const int nBatch = Nnext / (32 * 4 * 4);      // 4096/512 = 8

            float acc = 0.0f;
            #pragma unroll 1
            for (int it = 0; it < nBatch; ++it) {
                float4 w0 = __ldg(wr + 0 * 32);
                float4 w1 = __ldg(wr + 1 * 32);
                float4 w2 = __ldg(wr + 2 * 32);
                float4 w3 = __ldg(wr + 3 * 32);
                float4 v0 = __ldg(vv + 0 * 32);
                float4 v1 = __ldg(vv + 1 * 32);
                float4 v2 = __ldg(vv + 2 * 32);
                float4 v3 = __ldg(vv + 3 * 32);
                acc = fmaf(w0.x, v0.x, acc); acc = fmaf(w0.y, v0.y, acc);
                acc = fmaf(w0.z, v0.z, acc); acc = fmaf(w0.w, v0.w, acc);
                acc = fmaf(w1.x, v1.x, acc); acc = fmaf(w1.y, v1.y, acc);
                acc = fmaf(w1.z, v1.z, acc); acc = fmaf(w1.w, v1.w, acc);
                acc = fmaf(w2.x, v2.x, acc); acc = fmaf(w2.y, v2.y, acc);
                acc = fmaf(w2.z, v2.z, acc); acc = fmaf(w2.w, v2.w, acc);
                acc = fmaf(w3.x, v3.x, acc); acc = fmaf(w3.y, v3.y, acc);
                acc = fmaf(w3.z, v3.z, acc); acc = fmaf(w3.w, v3.w, acc);
                wr += 4 * 32;
                vv += 4 * 32;
            }
            #pragma unroll
            for (int o = 16; o > 0; o >>= 1)
                acc += __shfl_down_sync(0xFFFFFFFFu, acc, o);
            if (lane == 0) g_sV[row] = acc;
        } else {
            // ---- P / P_hat tile: 32 rows x 1024 cols ----
            const float* mat = (type == 1) ? P : Ph;
            float* out       = (type == 1) ? g_pP : g_pPh;

            const int col = (idx & 1) * 1024 + threadIdx.x * 4;
            const int r0  = (idx >> 1) * 32;

            const float4* m  = reinterpret_cast<const float4*>(mat + (size_t)r0 * K + col);
            const float4* p4 = reinterpret_cast<const float4*>(pi + r0);
            const size_t  s4 = (size_t)K / 4;

            float4 acc = make_float4(0.f, 0.f, 0.f, 0.f);
            #pragma unroll 1
            for (int rr = 0; rr < 32; rr += 8) {
                float4 w0 = __ldg(m + 0 * s4);
                float4 w1 = __ldg(m + 1 * s4);
                float4 w2 = __ldg(m + 2 * s4);
                float4 w3 = __ldg(m + 3 * s4);
                float4 w4 = __ldg(m + 4 * s4);
                float4 w5 = __ldg(m + 5 * s4);
                float4 w6 = __ldg(m + 6 * s4);
                float4 w7 = __ldg(m + 7 * s4);
                float4 pa = __ldg(p4 + 0);
                float4 pb = __ldg(p4 + 1);

                acc.x = fmaf(pa.x, w0.x, acc.x); acc.y = fmaf(pa.x, w0.y, acc.y);
                acc.z = fmaf(pa.x, w0.z, acc.z); acc.w = fmaf(pa.x, w0.w, acc.w);
                acc.x = fmaf(pa.y, w1.x, acc.x); acc.y = fmaf(pa.y, w1.y, acc.y);
                acc.z = fmaf(pa.y, w1.z, acc.z); acc.w = fmaf(pa.y, w1.w, acc.w);
                acc.x = fmaf(pa.z, w2.x, acc.x); acc.y = fmaf(pa.z, w2.y, acc.y);
                acc.z = fmaf(pa.z, w2.z, acc.z); acc.w = fmaf(pa.z, w2.w, acc.w);
                acc.x = fmaf(pa.w, w3.x, acc.x); acc.y = fmaf(pa.w, w3.y, acc.y);
                acc.z = fmaf(pa.w, w3.z, acc.z); acc.w = fmaf(pa.w, w3.w, acc.w);
                acc.x = fmaf(pb.x, w4.x, acc.x); acc.y = fmaf(pb.x, w4.y, acc.y);
                acc.z = fmaf(pb.x, w4.z, acc.z); acc.w = fmaf(pb.x, w4.w, acc.w);
                acc.x = fmaf(pb.y, w5.x, acc.x); acc.y = fmaf(pb.y, w5.y, acc.y);
                acc.z = fmaf(pb.y, w5.z, acc.z); acc.w = fmaf(pb.y, w5.w, acc.w);
                acc.x = fmaf(pb.z, w6.x, acc.x); acc.y = fmaf(pb.z, w6.y, acc.y);
                acc.z = fmaf(pb.z, w6.z, acc.z); acc.w = fmaf(pb.z, w6.w, acc.w);
                acc.x = fmaf(pb.w, w7.x, acc.x); acc.y = fmaf(pb.w, w7.y, acc.y);
                acc.z = fmaf(pb.w, w7.z, acc.z); acc.w = fmaf(pb.w, w7.w, acc.w);

                m  += 8 * s4;
                p4 += 2;
            }
            atomicAdd(&out[col + 0], acc.x);
            atomicAdd(&out[col + 1], acc.y);
            atomicAdd(&out[col + 2], acc.z);
            atomicAdd(&out[col + 3], acc.w);
        }
    }
}

// Parallel epilogue: 32 blocks x 128 threads, one neuron per thread.
// Each block counts unstable neurons in [0, blockStart) for its global rank
// offset, ballot-scans its own chunk, computes outputs, then re-zeros the
// g_pP/g_pPh rank-range it consumed (block-exclusive -> race-free).
__global__ __launch_bounds__(128)
void epilogue_kernel(const float* __restrict__ C, const float* __restrict__ L,
                     const float* __restrict__ U, const float* __restrict__ alpha,
                     float* __restrict__ out, int N, int K) {
    const int tid   = threadIdx.x;            // [0,128)
    const int lane  = tid & 31, warp = tid >> 5;
    const int start = blockIdx.x * 128;
    const int n     = start + tid;

    // ---- global rank offset: count unstable in [0, start) ----
    int pre = 0;
    for (int i = tid; i < start; i += 128) {
        float li = __ldg(L + i), ui = __ldg(U + i);
        pre += (li < 0.0f && ui > 0.0f);
    }
    // block reduce pre
    #pragma unroll
    for (int o = 16; o > 0; o >>= 1)
        pre += __shfl_down_sync(0xFFFFFFFFu, pre, o);
    __shared__ int wsum[4];
    __shared__ int wcnt[4];
    if (lane == 0) wsum[warp] = pre;

    // ---- own chunk mask + intra-chunk rank ----
    float l = 0.f, u = 0.f, c = 0.f;
    bool un = false;
    if (n < N) {
        l = __ldg(L + n); u = __ldg(U + n); c = __ldg(C + n);
        un = (l < 0.0f) && (u > 0.0f);
    }
    unsigned m = __ballot_sync(0xFFFFFFFFu, un);
    int before = __popc(m & ((1u << lane) - 1u));
    if (lane == 0) wcnt[warp] = __popc(m);
    __syncthreads();

    const int prefixBlk = wsum[0] + wsum[1] + wsum[2] + wsum[3];
    int woff = 0;
    #pragma unroll
    for (int w = 0; w < 4; ++w) woff += (w < warp) ? wcnt[w] : 0;
    const int chunkTotal = wcnt[0] + wcnt[1] + wcnt[2] + wcnt[3];
    const int k = prefixBlk + woff + before;

    if (n < N) {
        float val;
        if (un) {
            if (k < K) {
                float vhat = g_sV[n] - g_pPh[k];
                float rp   = fmaxf(vhat, 0.0f);
                float rn   = fmaxf(-vhat, 0.0f);
                val = rp * u / (u - l) - c - __ldg(alpha + k) * rn - g_pP[k];
            } else {
                val = 0.0f;
            }
        } else if (u <= 0.0f) {
            val = -c;                  // stably deactivated
        } else if (l >= 0.0f) {
            val = g_sV[n] - c;         // stably activated
        } else {
            val = 0.0f;
        }
        out[n] = val;
    }

    // ---- re-zero the rank-range this block consumed ----
    __syncthreads();
    for (int i = prefixBlk + tid; i < prefixBlk + chunkTotal; i += 128) {
        if (i < K) { g_pP[i] = 0.0f; g_pPh[i] = 0.0f; }
    }
}

extern "C" void kernel_launch(void* const* d_in, const int* in_sizes, int n_in,
                              void* d_out, int out_size) {
    const float* Vn    = (const float*)d_in[0];   // [N_NEXT]
    const float* W     = (const float*)d_in[1];   // [N_NEXT, N]
    const float* C     = (const float*)d_in[2];   // [N]
    const float* L     = (const float*)d_in[3];   // [N]
    const float* U     = (const float*)d_in[4];   // [N]
    const float* P     = (const float*)d_in[5];   // [P_ROWS, K]
    const float* Ph    = (const float*)d_in[6];   // [P_ROWS, K]
    const float* pi    = (const float*)d_in[7];   // [P_ROWS]
    const float* alpha = (const float*)d_in[8];   // [K]
    float* out = (float*)d_out;

    const int Nnext = in_sizes[0];
    const int N     = in_sizes[2];
    const int Prows = in_sizes[7];
    const int K     = in_sizes[8];

    const int G = 512;   // N/8 == 512 W tiles; (Prows/32)*(K/1024) == 512 P tiles each

    matvec_kernel<<<G, 256>>>(W, Vn, P, Ph, pi, N, Nnext, K, Prows, G);

    epilogue_kernel<<<(N + 127) / 128, 128>>>(C, L, U, alpha, out, N, K);
}